// round 1
// baseline (speedup 1.0000x reference)
#include <cuda_runtime.h>
#include <math.h>

// Problem constants
#define C_DIM  8
#define F_DIM  1024
#define W_DIM  512
#define H_DIM  16
#define D_DIM  64
#define FE_DIM 4096   // F * EXP

// ---------------------------------------------------------------------------
// Scratch (device globals; no allocation allowed)
// ---------------------------------------------------------------------------
__device__ float g_z [C_DIM * F_DIM * W_DIM];   // layernorm1 output
__device__ float g_p [C_DIM * F_DIM * W_DIM];   // q projection (= t = v)
__device__ float g_qr[C_DIM * F_DIM * W_DIM];   // rope(t) (= q = k)
__device__ float g_s [C_DIM * H_DIM * W_DIM * W_DIM]; // attention scores (128 MB)
__device__ float g_oP[C_DIM * F_DIM * W_DIM];   // attention output, [h*64+d][w] layout
__device__ float g_x2[C_DIM * F_DIM * W_DIM];   // x + attn
__device__ float g_z2[C_DIM * F_DIM * W_DIM];   // layernorm2 output
__device__ float g_h [C_DIM * FE_DIM * W_DIM];  // MLP hidden (64 MB)

// ---------------------------------------------------------------------------
// LayerNorm over F for each (c, w). Block = (32 w-lanes, 8 f-threads).
// ---------------------------------------------------------------------------
__global__ void layernorm_kernel(const float* __restrict__ x,
                                 const float* __restrict__ g,
                                 const float* __restrict__ b,
                                 float* __restrict__ out)
{
    int w  = blockIdx.x * 32 + threadIdx.x;
    int c  = blockIdx.y;
    int fz = threadIdx.y;
    const float* xp = x + (long long)c * F_DIM * W_DIM + w;
    float s = 0.f, ss = 0.f;
    for (int f = fz; f < F_DIM; f += 8) {
        float v = xp[(long long)f * W_DIM];
        s += v; ss += v * v;
    }
    __shared__ float sh_s[8][33], sh_q[8][33];
    sh_s[fz][threadIdx.x] = s;
    sh_q[fz][threadIdx.x] = ss;
    __syncthreads();
    if (fz == 0) {
        float ts = 0.f, tq = 0.f;
        #pragma unroll
        for (int i = 0; i < 8; i++) { ts += sh_s[i][threadIdx.x]; tq += sh_q[i][threadIdx.x]; }
        float mu  = ts * (1.f / F_DIM);
        float var = tq * (1.f / F_DIM) - mu * mu;
        sh_s[0][threadIdx.x] = mu;
        sh_q[0][threadIdx.x] = rsqrtf(var + 1e-5f);
    }
    __syncthreads();
    float mu = sh_s[0][threadIdx.x];
    float rs = sh_q[0][threadIdx.x];
    float* op = out + (long long)c * F_DIM * W_DIM + w;
    for (int f = fz; f < F_DIM; f += 8) {
        float v = xp[(long long)f * W_DIM];
        op[(long long)f * W_DIM] = (v - mu) * rs * g[f] + b[f];
    }
}

// ---------------------------------------------------------------------------
// RoPE: reads p[(c*1024 + h*64 + d)*512 + w], writes same layout.
// Only d<32 rotated; pair (2i, 2i+1) shares angle w * freqs[i], i<16.
// Block = (32 w-lanes, 8 pair-threads); grid = (W/32, C*H).
// ---------------------------------------------------------------------------
__global__ void rope_kernel(const float* __restrict__ p,
                            const float* __restrict__ freqs,
                            float* __restrict__ qr)
{
    int w  = blockIdx.x * 32 + threadIdx.x;
    int ch = blockIdx.y;                       // c*16 + h
    long long base = (long long)ch * D_DIM * W_DIM + w;
    for (int d2 = threadIdx.y; d2 < 32; d2 += 8) {
        float e = p[base + (long long)(2 * d2)     * W_DIM];
        float o = p[base + (long long)(2 * d2 + 1) * W_DIM];
        float qe, qo;
        if (d2 < 16) {
            float ang = (float)w * freqs[d2];
            float sn, cs;
            sincosf(ang, &sn, &cs);
            qe = e * cs - o * sn;
            qo = o * cs + e * sn;
        } else {
            qe = e; qo = o;
        }
        qr[base + (long long)(2 * d2)     * W_DIM] = qe;
        qr[base + (long long)(2 * d2 + 1) * W_DIM] = qo;
    }
}

// ---------------------------------------------------------------------------
// Row softmax over 512 elements, one warp per row. Block (32, 8).
// ---------------------------------------------------------------------------
__global__ void softmax_kernel(float* __restrict__ S)
{
    int row  = blockIdx.x * 8 + threadIdx.y;
    int lane = threadIdx.x;
    float* r = S + (long long)row * W_DIM;
    float v[16];
    float m = -1e30f;
    #pragma unroll
    for (int i = 0; i < 16; i++) { v[i] = r[lane + 32 * i]; m = fmaxf(m, v[i]); }
    #pragma unroll
    for (int off = 16; off; off >>= 1) m = fmaxf(m, __shfl_xor_sync(0xFFFFFFFFu, m, off));
    float s = 0.f;
    #pragma unroll
    for (int i = 0; i < 16; i++) { v[i] = __expf(v[i] - m); s += v[i]; }
    #pragma unroll
    for (int off = 16; off; off >>= 1) s += __shfl_xor_sync(0xFFFFFFFFu, s, off);
    float inv = 1.f / s;
    #pragma unroll
    for (int i = 0; i < 16; i++) r[lane + 32 * i] = v[i] * inv;
}

// ---------------------------------------------------------------------------
// Batched SGEMM, 128x128x8 tiles, 256 threads, 8x8 per-thread (split 4+4).
//   TA=false: A is M x K row-major.  TA=true: A is K x M row-major.
//   TB=false: B is K x N row-major.  TB=true: B is N x K row-major.
//   EPI: 0 = C = alpha*AB; 1 = C = alpha*AB + R; 2 = C = gelu(alpha*AB)
// Requirements: K%8==0, N%4==0; M may be ragged (guards).
// ---------------------------------------------------------------------------
__device__ __forceinline__ float gelu_f(float v)
{
    return 0.5f * v * (1.0f + erff(v * 0.70710678118654752f));
}

template<bool TA, bool TB, int EPI>
__global__ void __launch_bounds__(256, 2) sgemm_kernel(
    int M, int N, int K,
    const float* __restrict__ A, int lda, long long sA,
    const float* __restrict__ B, int ldb, long long sB,
    float* __restrict__ C, int ldc, long long sC,
    const float* __restrict__ R, long long sR,
    float alpha)
{
    __shared__ float As[8][128];
    __shared__ float Bs[8][128];
    A += (long long)blockIdx.z * sA;
    B += (long long)blockIdx.z * sB;
    C += (long long)blockIdx.z * sC;
    if (EPI == 1) R += (long long)blockIdx.z * sR;

    const int m0  = blockIdx.y * 128;
    const int n0  = blockIdx.x * 128;
    const int tid = threadIdx.x;
    const int ty  = tid >> 4;   // 0..15
    const int tx  = tid & 15;   // 0..15

    float acc[8][8];
    #pragma unroll
    for (int i = 0; i < 8; i++)
        #pragma unroll
        for (int j = 0; j < 8; j++)
            acc[i][j] = 0.f;

    for (int k0 = 0; k0 < K; k0 += 8) {
        // ---- load A tile into As[k][m] ----
        if (!TA) {
            int row = tid >> 1, col = (tid & 1) * 4;      // row: m, col: k
            float4 v = make_float4(0.f, 0.f, 0.f, 0.f);
            if (m0 + row < M)
                v = *reinterpret_cast<const float4*>(A + (long long)(m0 + row) * lda + (k0 + col));
            As[col + 0][row] = v.x; As[col + 1][row] = v.y;
            As[col + 2][row] = v.z; As[col + 3][row] = v.w;
        } else {
            int row = tid >> 5, col = (tid & 31) * 4;     // row: k, col: m
            float4 v = make_float4(0.f, 0.f, 0.f, 0.f);
            if (m0 + col < M)
                v = *reinterpret_cast<const float4*>(A + (long long)(k0 + row) * lda + (m0 + col));
            *reinterpret_cast<float4*>(&As[row][col]) = v;
        }
        // ---- load B tile into Bs[k][n] ----
        if (!TB) {
            int row = tid >> 5, col = (tid & 31) * 4;     // row: k, col: n
            float4 v = make_float4(0.f, 0.f, 0.f, 0.f);
            if (n0 + col < N)
                v = *reinterpret_cast<const float4*>(B + (long long)(k0 + row) * ldb + (n0 + col));
            *reinterpret_cast<float4*>(&Bs[row][col]) = v;
        } else {
            int row = tid >> 1, col = (tid & 1) * 4;      // row: n, col: k
            float4 v = make_float4(0.f, 0.f, 0.f, 0.f);
            if (n0 + row < N)
                v = *reinterpret_cast<const float4*>(B + (long long)(n0 + row) * ldb + (k0 + col));
            Bs[col + 0][row] = v.x; Bs[col + 1][row] = v.y;
            Bs[col + 2][row] = v.z; Bs[col + 3][row] = v.w;
        }
        __syncthreads();

        #pragma unroll
        for (int kk = 0; kk < 8; kk++) {
            float a[8], b[8];
            *reinterpret_cast<float4*>(&a[0]) = *reinterpret_cast<float4*>(&As[kk][ty * 4]);
            *reinterpret_cast<float4*>(&a[4]) = *reinterpret_cast<float4*>(&As[kk][64 + ty * 4]);
            *reinterpret_cast<float4*>(&b[0]) = *reinterpret_cast<float4*>(&Bs[kk][tx * 4]);
            *reinterpret_cast<float4*>(&b[4]) = *reinterpret_cast<float4*>(&Bs[kk][64 + tx * 4]);
            #pragma unroll
            for (int i = 0; i < 8; i++)
                #pragma unroll
                for (int j = 0; j < 8; j++)
                    acc[i][j] += a[i] * b[j];
        }
        __syncthreads();
    }

    // ---- epilogue ----
    #pragma unroll
    for (int i = 0; i < 8; i++) {
        int m = m0 + ((i < 4) ? (ty * 4 + i) : (64 + ty * 4 + (i - 4)));
        if (m >= M) continue;
        #pragma unroll
        for (int jg = 0; jg < 2; jg++) {
            int n = n0 + ((jg == 0) ? (tx * 4) : (64 + tx * 4));
            if (n >= N) continue;
            long long off = (long long)m * ldc + n;
            float4 v;
            v.x = acc[i][jg * 4 + 0] * alpha;
            v.y = acc[i][jg * 4 + 1] * alpha;
            v.z = acc[i][jg * 4 + 2] * alpha;
            v.w = acc[i][jg * 4 + 3] * alpha;
            if (EPI == 1) {
                float4 r = *reinterpret_cast<const float4*>(R + off);
                v.x += r.x; v.y += r.y; v.z += r.z; v.w += r.w;
            }
            if (EPI == 2) {
                v.x = gelu_f(v.x); v.y = gelu_f(v.y);
                v.z = gelu_f(v.z); v.w = gelu_f(v.w);
            }
            *reinterpret_cast<float4*>(C + off) = v;
        }
    }
}

// ---------------------------------------------------------------------------
// Launch
// ---------------------------------------------------------------------------
extern "C" void kernel_launch(void* const* d_in, const int* in_sizes, int n_in,
                              void* d_out, int out_size)
{
    (void)in_sizes; (void)n_in; (void)out_size;
    const float* x   = (const float*)d_in[0];
    const float* g1  = (const float*)d_in[1];
    const float* b1  = (const float*)d_in[2];
    const float* wq  = (const float*)d_in[3];
    const float* wo  = (const float*)d_in[4];
    const float* fr  = (const float*)d_in[5];
    const float* g2  = (const float*)d_in[6];
    const float* b2  = (const float*)d_in[7];
    const float* w1  = (const float*)d_in[8];
    const float* w2  = (const float*)d_in[9];
    float* out = (float*)d_out;

    float *z, *p, *qr, *s, *oP, *x2, *z2, *h;
    cudaGetSymbolAddress((void**)&z,  g_z);
    cudaGetSymbolAddress((void**)&p,  g_p);
    cudaGetSymbolAddress((void**)&qr, g_qr);
    cudaGetSymbolAddress((void**)&s,  g_s);
    cudaGetSymbolAddress((void**)&oP, g_oP);
    cudaGetSymbolAddress((void**)&x2, g_x2);
    cudaGetSymbolAddress((void**)&z2, g_z2);
    cudaGetSymbolAddress((void**)&h,  g_h);

    const long long sFW  = (long long)F_DIM * W_DIM;        // 524288
    const long long sHD  = (long long)D_DIM * W_DIM;        // 32768 (per-head)
    const long long sS   = (long long)W_DIM * W_DIM;        // 262144
    const long long sWqq = (long long)F_DIM * F_DIM;        // 1048576
    const long long sW1  = (long long)FE_DIM * F_DIM;       // 4194304
    const long long sH   = (long long)FE_DIM * W_DIM;       // 2097152

    dim3 ln_grid(W_DIM / 32, C_DIM), ln_blk(32, 8);

    // 1. z = frame_norm(x)
    layernorm_kernel<<<ln_grid, ln_blk>>>(x, g1, b1, z);

    // 2. p = Wq @ z   (per channel, M=1024 N=512 K=1024)
    sgemm_kernel<false, false, 0><<<dim3(4, 8, 8), 256>>>(
        1024, 512, 1024, wq, 1024, sWqq, z, 512, sFW, p, 512, sFW, nullptr, 0, 1.f);

    // 3. qr = rope(p)
    rope_kernel<<<dim3(W_DIM / 32, C_DIM * H_DIM), dim3(32, 8)>>>(p, fr, qr);

    // 4. S = (qr^T qr) / 32   (TN, per head: M=N=512 K=64, 128 batches)
    sgemm_kernel<true, false, 0><<<dim3(4, 4, 128), 256>>>(
        512, 512, 64, qr, 512, sHD, qr, 512, sHD, s, 512, sS, nullptr, 0, 0.03125f);

    // 5. softmax rows
    softmax_kernel<<<(C_DIM * H_DIM * W_DIM) / 8, dim3(32, 8)>>>(s);

    // 6. oP[d, q] = sum_k V[d,k] * S[q,k]   (NT, M=64 N=512 K=512; V = p)
    sgemm_kernel<false, true, 0><<<dim3(4, 1, 128), 256>>>(
        64, 512, 512, p, 512, sHD, s, 512, sS, oP, 512, sHD, nullptr, 0, 1.f);

    // 7. x2 = x + Wo @ oP
    sgemm_kernel<false, false, 1><<<dim3(4, 8, 8), 256>>>(
        1024, 512, 1024, wo, 1024, sWqq, oP, 512, sFW, x2, 512, sFW, x, sFW, 1.f);

    // 8. z2 = frame_norm(x2)
    layernorm_kernel<<<ln_grid, ln_blk>>>(x2, g2, b2, z2);

    // 9. h = gelu(W1 @ z2)   (M=4096 N=512 K=1024)
    sgemm_kernel<false, false, 2><<<dim3(4, 32, 8), 256>>>(
        4096, 512, 1024, w1, 1024, sW1, z2, 512, sFW, h, 512, sH, nullptr, 0, 1.f);

    // 10. out = x2 + W2 @ h   (M=1024 N=512 K=4096)
    sgemm_kernel<false, false, 1><<<dim3(4, 8, 8), 256>>>(
        1024, 512, 4096, w2, 4096, sW1, h, 512, sH, out, 512, sFW, x2, sFW, 1.f);
}

// round 2
// speedup vs baseline: 2.6082x; 2.6082x over previous
#include <cuda_runtime.h>
#include <math.h>

// Problem constants
#define C_DIM  8
#define F_DIM  1024
#define W_DIM  512
#define H_DIM  16
#define D_DIM  64
#define FE_DIM 4096   // F * EXP

// ---------------------------------------------------------------------------
// Scratch (device globals; no allocation allowed)
// ---------------------------------------------------------------------------
__device__ float g_z [C_DIM * F_DIM * W_DIM];   // layernorm1 output
__device__ float g_p [C_DIM * F_DIM * W_DIM];   // q projection (= t = v)
__device__ float g_qr[C_DIM * F_DIM * W_DIM];   // rope(t) (= q = k)
__device__ float g_s [C_DIM * H_DIM * W_DIM * W_DIM]; // attention scores (128 MB)
__device__ float g_oP[C_DIM * F_DIM * W_DIM];   // attention output, [h*64+d][w] layout
__device__ float g_x2[C_DIM * F_DIM * W_DIM];   // x + attn
__device__ float g_z2[C_DIM * F_DIM * W_DIM];   // layernorm2 output
__device__ float g_h [C_DIM * FE_DIM * W_DIM];  // MLP hidden (64 MB)

// ---------------------------------------------------------------------------
// PTX helpers
// ---------------------------------------------------------------------------
__device__ __forceinline__ void cp16(float* dst, const float* src, bool p)
{
    unsigned int d = (unsigned int)__cvta_generic_to_shared(dst);
    int sz = p ? 16 : 0;
    asm volatile("cp.async.ca.shared.global [%0], [%1], 16, %2;\n"
                 :: "r"(d), "l"(src), "r"(sz));
}
__device__ __forceinline__ void cp_commit()
{
    asm volatile("cp.async.commit_group;\n" ::: "memory");
}
__device__ __forceinline__ void cp_wait1()
{
    asm volatile("cp.async.wait_group 1;\n" ::: "memory");
}
__device__ __forceinline__ void cp_wait0()
{
    asm volatile("cp.async.wait_group 0;\n" ::: "memory");
}
__device__ __forceinline__ unsigned int tf32r(float x)
{
    unsigned int r;
    asm("cvt.rna.tf32.f32 %0, %1;\n" : "=r"(r) : "f"(x));
    return r;
}
__device__ __forceinline__ void mma8(float* c, const unsigned int* a, const unsigned int* b)
{
    asm volatile(
        "mma.sync.aligned.m16n8k8.row.col.f32.tf32.tf32.f32 "
        "{%0,%1,%2,%3}, {%4,%5,%6,%7}, {%8,%9}, {%0,%1,%2,%3};\n"
        : "+f"(c[0]), "+f"(c[1]), "+f"(c[2]), "+f"(c[3])
        : "r"(a[0]), "r"(a[1]), "r"(a[2]), "r"(a[3]), "r"(b[0]), "r"(b[1]));
}
__device__ __forceinline__ float gelu_f(float v)
{
    return 0.5f * v * (1.0f + erff(v * 0.70710678118654752f));
}

// ---------------------------------------------------------------------------
// TF32 tensor-core GEMM. Block tile 128x128, KC=16, double-buffered cp.async.
// 256 threads = 8 warps (4 in m x 2 in n), warp tile 32x64, mma.m16n8k8.
//
// LAYA=0: A gmem row-major [M][K]   -> smem As[m][k], stride 20 (pad)
// LAYA=1: A gmem col-major [K][M]   -> smem As[k][m], stride 136 (pad)
// LAYB=0: B gmem row-major [K][N]   -> smem Bs[k][n], stride 136
// LAYB=1: B gmem row-major [N][K]   -> smem Bs[n][k], stride 20
// EPI: 0: C = alpha*AB;  1: C = alpha*AB + R;  2: C = gelu(alpha*AB)
// Requires: K%16==0, N%128==0. M may be ragged (guards).
// ---------------------------------------------------------------------------
template<int LAYA, int LAYB, int EPI>
__global__ void __launch_bounds__(256) tgemm_kernel(
    int M, int N, int K,
    const float* __restrict__ A, int lda, long long strA,
    const float* __restrict__ B, int ldb, long long strB,
    float* __restrict__ C, int ldc, long long strC,
    const float* __restrict__ R, long long strR,
    float alpha)
{
    __shared__ float sA[2][2560];
    __shared__ float sB[2][2560];

    A += (long long)blockIdx.z * strA;
    B += (long long)blockIdx.z * strB;
    C += (long long)blockIdx.z * strC;
    if (EPI == 1) R += (long long)blockIdx.z * strR;

    const int m0   = blockIdx.y * 128;
    const int n0   = blockIdx.x * 128;
    const int tid  = threadIdx.x;
    const int lane = tid & 31;
    const int wid  = tid >> 5;
    const int m0w  = (wid & 3) * 32;
    const int n0w  = (wid >> 2) * 64;
    const int g    = lane >> 2;   // group id 0..7
    const int tg   = lane & 3;    // thread-in-group 0..3

    float acc[2][8][4];
    #pragma unroll
    for (int mi = 0; mi < 2; mi++)
        #pragma unroll
        for (int ni = 0; ni < 8; ni++)
            #pragma unroll
            for (int q = 0; q < 4; q++)
                acc[mi][ni][q] = 0.f;

    auto copy_stage = [&](int st, int k0) {
        #pragma unroll
        for (int r = 0; r < 2; r++) {
            int f = tid + r * 256;
            if (LAYA == 0) {
                int m = f >> 2, k4 = (f & 3) * 4;
                cp16(&sA[st][m * 20 + k4],
                     A + (long long)(m0 + m) * lda + k0 + k4, (m0 + m) < M);
            } else {
                int k = f >> 5, m4 = (f & 31) * 4;
                cp16(&sA[st][k * 136 + m4],
                     A + (long long)(k0 + k) * lda + m0 + m4, (m0 + m4) < M);
            }
        }
        #pragma unroll
        for (int r = 0; r < 2; r++) {
            int f = tid + r * 256;
            if (LAYB == 0) {
                int k = f >> 5, n4 = (f & 31) * 4;
                cp16(&sB[st][k * 136 + n4],
                     B + (long long)(k0 + k) * ldb + n0 + n4, true);
            } else {
                int n = f >> 2, k4 = (f & 3) * 4;
                cp16(&sB[st][n * 20 + k4],
                     B + (long long)(n0 + n) * ldb + k0 + k4, true);
            }
        }
        cp_commit();
    };

    auto compute_stage = [&](int st) {
        #pragma unroll
        for (int ks = 0; ks < 2; ks++) {
            const int kk = ks * 8;
            unsigned int a[2][4];
            #pragma unroll
            for (int mi = 0; mi < 2; mi++) {
                const int mm = m0w + 16 * mi + g;
                if (LAYA == 0) {
                    const float* p = &sA[st][mm * 20 + kk + tg];
                    a[mi][0] = tf32r(p[0]);
                    a[mi][1] = tf32r(p[8 * 20]);
                    a[mi][2] = tf32r(p[4]);
                    a[mi][3] = tf32r(p[8 * 20 + 4]);
                } else {
                    const float* p = &sA[st][(kk + tg) * 136 + mm];
                    a[mi][0] = tf32r(p[0]);
                    a[mi][1] = tf32r(p[8]);
                    a[mi][2] = tf32r(p[4 * 136]);
                    a[mi][3] = tf32r(p[4 * 136 + 8]);
                }
            }
            #pragma unroll
            for (int ni = 0; ni < 8; ni++) {
                const int nn = n0w + 8 * ni + g;
                unsigned int b[2];
                if (LAYB == 0) {
                    const float* p = &sB[st][(kk + tg) * 136 + nn];
                    b[0] = tf32r(p[0]);
                    b[1] = tf32r(p[4 * 136]);
                } else {
                    const float* p = &sB[st][nn * 20 + kk + tg];
                    b[0] = tf32r(p[0]);
                    b[1] = tf32r(p[4]);
                }
                mma8(acc[0][ni], a[0], b);
                mma8(acc[1][ni], a[1], b);
            }
        }
    };

    const int nch = K / 16;
    copy_stage(0, 0);
    for (int ch = 0; ch < nch; ch++) {
        if (ch + 1 < nch) {
            copy_stage((ch + 1) & 1, (ch + 1) * 16);
            cp_wait1();
        } else {
            cp_wait0();
        }
        __syncthreads();
        compute_stage(ch & 1);
        __syncthreads();
    }

    // ---- epilogue ----
    #pragma unroll
    for (int mi = 0; mi < 2; mi++) {
        const int mr = m0 + m0w + 16 * mi + g;
        #pragma unroll
        for (int ni = 0; ni < 8; ni++) {
            const int nc = n0 + n0w + 8 * ni + 2 * tg;
            float2 v0, v1;
            v0.x = acc[mi][ni][0] * alpha; v0.y = acc[mi][ni][1] * alpha;
            v1.x = acc[mi][ni][2] * alpha; v1.y = acc[mi][ni][3] * alpha;
            if (EPI == 1) {
                if (mr < M) {
                    float2 r0 = *reinterpret_cast<const float2*>(R + (long long)mr * ldc + nc);
                    v0.x += r0.x; v0.y += r0.y;
                }
                if (mr + 8 < M) {
                    float2 r1 = *reinterpret_cast<const float2*>(R + (long long)(mr + 8) * ldc + nc);
                    v1.x += r1.x; v1.y += r1.y;
                }
            }
            if (EPI == 2) {
                v0.x = gelu_f(v0.x); v0.y = gelu_f(v0.y);
                v1.x = gelu_f(v1.x); v1.y = gelu_f(v1.y);
            }
            if (mr < M)
                *reinterpret_cast<float2*>(C + (long long)mr * ldc + nc) = v0;
            if (mr + 8 < M)
                *reinterpret_cast<float2*>(C + (long long)(mr + 8) * ldc + nc) = v1;
        }
    }
}

// ---------------------------------------------------------------------------
// LayerNorm over F for each (c, w). Block = (32 w-lanes, 8 f-threads).
// ---------------------------------------------------------------------------
__global__ void layernorm_kernel(const float* __restrict__ x,
                                 const float* __restrict__ g,
                                 const float* __restrict__ b,
                                 float* __restrict__ out)
{
    int w  = blockIdx.x * 32 + threadIdx.x;
    int c  = blockIdx.y;
    int fz = threadIdx.y;
    const float* xp = x + (long long)c * F_DIM * W_DIM + w;
    float s = 0.f, ss = 0.f;
    for (int f = fz; f < F_DIM; f += 8) {
        float v = xp[(long long)f * W_DIM];
        s += v; ss += v * v;
    }
    __shared__ float sh_s[8][33], sh_q[8][33];
    sh_s[fz][threadIdx.x] = s;
    sh_q[fz][threadIdx.x] = ss;
    __syncthreads();
    if (fz == 0) {
        float ts = 0.f, tq = 0.f;
        #pragma unroll
        for (int i = 0; i < 8; i++) { ts += sh_s[i][threadIdx.x]; tq += sh_q[i][threadIdx.x]; }
        float mu  = ts * (1.f / F_DIM);
        float var = tq * (1.f / F_DIM) - mu * mu;
        sh_s[0][threadIdx.x] = mu;
        sh_q[0][threadIdx.x] = rsqrtf(var + 1e-5f);
    }
    __syncthreads();
    float mu = sh_s[0][threadIdx.x];
    float rs = sh_q[0][threadIdx.x];
    float* op = out + (long long)c * F_DIM * W_DIM + w;
    for (int f = fz; f < F_DIM; f += 8) {
        float v = xp[(long long)f * W_DIM];
        op[(long long)f * W_DIM] = (v - mu) * rs * g[f] + b[f];
    }
}

// ---------------------------------------------------------------------------
// RoPE: reads p[(c*1024 + h*64 + d)*512 + w], writes same layout.
// ---------------------------------------------------------------------------
__global__ void rope_kernel(const float* __restrict__ p,
                            const float* __restrict__ freqs,
                            float* __restrict__ qr)
{
    int w  = blockIdx.x * 32 + threadIdx.x;
    int ch = blockIdx.y;                       // c*16 + h
    long long base = (long long)ch * D_DIM * W_DIM + w;
    for (int d2 = threadIdx.y; d2 < 32; d2 += 8) {
        float e = p[base + (long long)(2 * d2)     * W_DIM];
        float o = p[base + (long long)(2 * d2 + 1) * W_DIM];
        float qe, qo;
        if (d2 < 16) {
            float ang = (float)w * freqs[d2];
            float sn, cs;
            sincosf(ang, &sn, &cs);
            qe = e * cs - o * sn;
            qo = o * cs + e * sn;
        } else {
            qe = e; qo = o;
        }
        qr[base + (long long)(2 * d2)     * W_DIM] = qe;
        qr[base + (long long)(2 * d2 + 1) * W_DIM] = qo;
    }
}

// ---------------------------------------------------------------------------
// Row softmax over 512 elements, one warp per row. Block (32, 8).
// ---------------------------------------------------------------------------
__global__ void softmax_kernel(float* __restrict__ S)
{
    int row  = blockIdx.x * 8 + threadIdx.y;
    int lane = threadIdx.x;
    float* r = S + (long long)row * W_DIM;
    float v[16];
    float m = -1e30f;
    #pragma unroll
    for (int i = 0; i < 16; i++) { v[i] = r[lane + 32 * i]; m = fmaxf(m, v[i]); }
    #pragma unroll
    for (int off = 16; off; off >>= 1) m = fmaxf(m, __shfl_xor_sync(0xFFFFFFFFu, m, off));
    float s = 0.f;
    #pragma unroll
    for (int i = 0; i < 16; i++) { v[i] = __expf(v[i] - m); s += v[i]; }
    #pragma unroll
    for (int off = 16; off; off >>= 1) s += __shfl_xor_sync(0xFFFFFFFFu, s, off);
    float inv = 1.f / s;
    #pragma unroll
    for (int i = 0; i < 16; i++) r[lane + 32 * i] = v[i] * inv;
}

// ---------------------------------------------------------------------------
// Launch
// ---------------------------------------------------------------------------
extern "C" void kernel_launch(void* const* d_in, const int* in_sizes, int n_in,
                              void* d_out, int out_size)
{
    (void)in_sizes; (void)n_in; (void)out_size;
    const float* x   = (const float*)d_in[0];
    const float* g1  = (const float*)d_in[1];
    const float* b1  = (const float*)d_in[2];
    const float* wq  = (const float*)d_in[3];
    const float* wo  = (const float*)d_in[4];
    const float* fr  = (const float*)d_in[5];
    const float* g2  = (const float*)d_in[6];
    const float* b2  = (const float*)d_in[7];
    const float* w1  = (const float*)d_in[8];
    const float* w2  = (const float*)d_in[9];
    float* out = (float*)d_out;

    float *z, *p, *qr, *s, *oP, *x2, *z2, *h;
    cudaGetSymbolAddress((void**)&z,  g_z);
    cudaGetSymbolAddress((void**)&p,  g_p);
    cudaGetSymbolAddress((void**)&qr, g_qr);
    cudaGetSymbolAddress((void**)&s,  g_s);
    cudaGetSymbolAddress((void**)&oP, g_oP);
    cudaGetSymbolAddress((void**)&x2, g_x2);
    cudaGetSymbolAddress((void**)&z2, g_z2);
    cudaGetSymbolAddress((void**)&h,  g_h);

    const long long sFW  = (long long)F_DIM * W_DIM;        // 524288
    const long long sHD  = (long long)D_DIM * W_DIM;        // 32768 (per-head)
    const long long sS   = (long long)W_DIM * W_DIM;        // 262144
    const long long sWqq = (long long)F_DIM * F_DIM;        // 1048576
    const long long sW1  = (long long)FE_DIM * F_DIM;       // 4194304
    const long long sH   = (long long)FE_DIM * W_DIM;       // 2097152

    dim3 ln_grid(W_DIM / 32, C_DIM), ln_blk(32, 8);

    // 1. z = frame_norm(x)
    layernorm_kernel<<<ln_grid, ln_blk>>>(x, g1, b1, z);

    // 2. p = Wq @ z   (per channel, M=1024 N=512 K=1024, NN)
    tgemm_kernel<0, 0, 0><<<dim3(4, 8, 8), 256>>>(
        1024, 512, 1024, wq, 1024, sWqq, z, 512, sFW, p, 512, sFW, nullptr, 0, 1.f);

    // 3. qr = rope(p)
    rope_kernel<<<dim3(W_DIM / 32, C_DIM * H_DIM), dim3(32, 8)>>>(p, fr, qr);

    // 4. S = (qr^T qr) / 32   (TN, per head: M=N=512 K=64, 128 batches)
    tgemm_kernel<1, 0, 0><<<dim3(4, 4, 128), 256>>>(
        512, 512, 64, qr, 512, sHD, qr, 512, sHD, s, 512, sS, nullptr, 0, 0.03125f);

    // 5. softmax rows
    softmax_kernel<<<(C_DIM * H_DIM * W_DIM) / 8, dim3(32, 8)>>>(s);

    // 6. oP[d, q] = sum_k V[d,k] * S[q,k]   (NT, M=64 N=512 K=512; V = p)
    tgemm_kernel<0, 1, 0><<<dim3(4, 1, 128), 256>>>(
        64, 512, 512, p, 512, sHD, s, 512, sS, oP, 512, sHD, nullptr, 0, 1.f);

    // 7. x2 = x + Wo @ oP
    tgemm_kernel<0, 0, 1><<<dim3(4, 8, 8), 256>>>(
        1024, 512, 1024, wo, 1024, sWqq, oP, 512, sFW, x2, 512, sFW, x, sFW, 1.f);

    // 8. z2 = frame_norm(x2)
    layernorm_kernel<<<ln_grid, ln_blk>>>(x2, g2, b2, z2);

    // 9. h = gelu(W1 @ z2)   (M=4096 N=512 K=1024)
    tgemm_kernel<0, 0, 2><<<dim3(4, 32, 8), 256>>>(
        4096, 512, 1024, w1, 1024, sW1, z2, 512, sFW, h, 512, sH, nullptr, 0, 1.f);

    // 10. out = x2 + W2 @ h   (M=1024 N=512 K=4096)
    tgemm_kernel<0, 0, 1><<<dim3(4, 8, 8), 256>>>(
        1024, 512, 4096, w2, 4096, sW1, h, 512, sH, out, 512, sFW, x2, sFW, 1.f);
}

// round 3
// speedup vs baseline: 2.6213x; 1.0050x over previous
#include <cuda_runtime.h>
#include <math.h>

// Problem constants
#define C_DIM  8
#define F_DIM  1024
#define W_DIM  512
#define H_DIM  16
#define D_DIM  64
#define FE_DIM 4096   // F * EXP

// ---------------------------------------------------------------------------
// Scratch (device globals; no allocation allowed)
// ---------------------------------------------------------------------------
__device__ float g_z [C_DIM * F_DIM * W_DIM];   // layernorm1 output
__device__ float g_p [C_DIM * F_DIM * W_DIM];   // q projection (= t = v)
__device__ float g_qr[C_DIM * F_DIM * W_DIM];   // rope(t) (= q = k)
__device__ float g_s [C_DIM * H_DIM * W_DIM * W_DIM]; // attention scores (128 MB)
__device__ float g_oP[C_DIM * F_DIM * W_DIM];   // attention output, [h*64+d][w] layout
__device__ float g_x2[C_DIM * F_DIM * W_DIM];   // x + attn
__device__ float g_z2[C_DIM * F_DIM * W_DIM];   // layernorm2 output
__device__ float g_h [C_DIM * FE_DIM * W_DIM];  // MLP hidden (64 MB)

// ---------------------------------------------------------------------------
// PTX helpers
// ---------------------------------------------------------------------------
__device__ __forceinline__ void cp16(float* dst, const float* src, bool p)
{
    unsigned int d = (unsigned int)__cvta_generic_to_shared(dst);
    int sz = p ? 16 : 0;
    asm volatile("cp.async.ca.shared.global [%0], [%1], 16, %2;\n"
                 :: "r"(d), "l"(src), "r"(sz));
}
__device__ __forceinline__ void cp_commit()
{
    asm volatile("cp.async.commit_group;\n" ::: "memory");
}
__device__ __forceinline__ void cp_wait1()
{
    asm volatile("cp.async.wait_group 1;\n" ::: "memory");
}
__device__ __forceinline__ void cp_wait0()
{
    asm volatile("cp.async.wait_group 0;\n" ::: "memory");
}
__device__ __forceinline__ unsigned int tf32r(float x)
{
    unsigned int r;
    asm("cvt.rna.tf32.f32 %0, %1;\n" : "=r"(r) : "f"(x));
    return r;
}
__device__ __forceinline__ void mma8(float* c, const unsigned int* a, const unsigned int* b)
{
    asm volatile(
        "mma.sync.aligned.m16n8k8.row.col.f32.tf32.tf32.f32 "
        "{%0,%1,%2,%3}, {%4,%5,%6,%7}, {%8,%9}, {%0,%1,%2,%3};\n"
        : "+f"(c[0]), "+f"(c[1]), "+f"(c[2]), "+f"(c[3])
        : "r"(a[0]), "r"(a[1]), "r"(a[2]), "r"(a[3]), "r"(b[0]), "r"(b[1]));
}
__device__ __forceinline__ float gelu_f(float v)
{
    return 0.5f * v * (1.0f + erff(v * 0.70710678118654752f));
}

// ---------------------------------------------------------------------------
// TF32 tensor-core GEMM. Block tile 128x128, KC=16, double-buffered cp.async.
// 256 threads = 8 warps (4 in m x 2 in n), warp tile 32x64, mma.m16n8k8.
//
// LAYA=0: A gmem row-major [M][K]   -> smem As[m][k], stride 20 (pad)
// LAYA=1: A gmem col-major [K][M]   -> smem As[k][m], stride 136 (pad)
// LAYB=0: B gmem row-major [K][N]   -> smem Bs[k][n], stride 136
// LAYB=1: B gmem row-major [N][K]   -> smem Bs[n][k], stride 20
// EPI: 0: C = alpha*AB;  1: C = alpha*AB + R;  2: C = gelu(alpha*AB)
// Requires: K%16==0, N%128==0. M may be ragged (guards).
// ---------------------------------------------------------------------------
template<int LAYA, int LAYB, int EPI>
__global__ void __launch_bounds__(256) tgemm_kernel(
    int M, int N, int K,
    const float* __restrict__ A, int lda, long long strA,
    const float* __restrict__ B, int ldb, long long strB,
    float* __restrict__ C, int ldc, long long strC,
    const float* __restrict__ R, long long strR,
    float alpha)
{
    __shared__ float sA[2][2560];
    __shared__ float sB[2][2560];

    A += (long long)blockIdx.z * strA;
    B += (long long)blockIdx.z * strB;
    C += (long long)blockIdx.z * strC;
    if (EPI == 1) R += (long long)blockIdx.z * strR;

    const int m0   = blockIdx.y * 128;
    const int n0   = blockIdx.x * 128;
    const int tid  = threadIdx.x;
    const int lane = tid & 31;
    const int wid  = tid >> 5;
    const int m0w  = (wid & 3) * 32;
    const int n0w  = (wid >> 2) * 64;
    const int g    = lane >> 2;   // group id 0..7
    const int tg   = lane & 3;    // thread-in-group 0..3

    float acc[2][8][4];
    #pragma unroll
    for (int mi = 0; mi < 2; mi++)
        #pragma unroll
        for (int ni = 0; ni < 8; ni++)
            #pragma unroll
            for (int q = 0; q < 4; q++)
                acc[mi][ni][q] = 0.f;

    auto copy_stage = [&](int st, int k0) {
        #pragma unroll
        for (int r = 0; r < 2; r++) {
            int f = tid + r * 256;
            if (LAYA == 0) {
                int m = f >> 2, k4 = (f & 3) * 4;
                cp16(&sA[st][m * 20 + k4],
                     A + (long long)(m0 + m) * lda + k0 + k4, (m0 + m) < M);
            } else {
                int k = f >> 5, m4 = (f & 31) * 4;
                cp16(&sA[st][k * 136 + m4],
                     A + (long long)(k0 + k) * lda + m0 + m4, (m0 + m4) < M);
            }
        }
        #pragma unroll
        for (int r = 0; r < 2; r++) {
            int f = tid + r * 256;
            if (LAYB == 0) {
                int k = f >> 5, n4 = (f & 31) * 4;
                cp16(&sB[st][k * 136 + n4],
                     B + (long long)(k0 + k) * ldb + n0 + n4, true);
            } else {
                int n = f >> 2, k4 = (f & 3) * 4;
                cp16(&sB[st][n * 20 + k4],
                     B + (long long)(n0 + n) * ldb + k0 + k4, true);
            }
        }
        cp_commit();
    };

    auto compute_stage = [&](int st) {
        #pragma unroll
        for (int ks = 0; ks < 2; ks++) {
            const int kk = ks * 8;
            unsigned int a[2][4];
            #pragma unroll
            for (int mi = 0; mi < 2; mi++) {
                const int mm = m0w + 16 * mi + g;
                if (LAYA == 0) {
                    const float* p = &sA[st][mm * 20 + kk + tg];
                    a[mi][0] = tf32r(p[0]);
                    a[mi][1] = tf32r(p[8 * 20]);
                    a[mi][2] = tf32r(p[4]);
                    a[mi][3] = tf32r(p[8 * 20 + 4]);
                } else {
                    const float* p = &sA[st][(kk + tg) * 136 + mm];
                    a[mi][0] = tf32r(p[0]);
                    a[mi][1] = tf32r(p[8]);
                    a[mi][2] = tf32r(p[4 * 136]);
                    a[mi][3] = tf32r(p[4 * 136 + 8]);
                }
            }
            #pragma unroll
            for (int ni = 0; ni < 8; ni++) {
                const int nn = n0w + 8 * ni + g;
                unsigned int b[2];
                if (LAYB == 0) {
                    const float* p = &sB[st][(kk + tg) * 136 + nn];
                    b[0] = tf32r(p[0]);
                    b[1] = tf32r(p[4 * 136]);
                } else {
                    const float* p = &sB[st][nn * 20 + kk + tg];
                    b[0] = tf32r(p[0]);
                    b[1] = tf32r(p[4]);
                }
                mma8(acc[0][ni], a[0], b);
                mma8(acc[1][ni], a[1], b);
            }
        }
    };

    const int nch = K / 16;
    copy_stage(0, 0);
    for (int ch = 0; ch < nch; ch++) {
        if (ch + 1 < nch) {
            copy_stage((ch + 1) & 1, (ch + 1) * 16);
            cp_wait1();
        } else {
            cp_wait0();
        }
        __syncthreads();
        compute_stage(ch & 1);
        __syncthreads();
    }

    // ---- epilogue ----
    #pragma unroll
    for (int mi = 0; mi < 2; mi++) {
        const int mr = m0 + m0w + 16 * mi + g;
        #pragma unroll
        for (int ni = 0; ni < 8; ni++) {
            const int nc = n0 + n0w + 8 * ni + 2 * tg;
            float2 v0, v1;
            v0.x = acc[mi][ni][0] * alpha; v0.y = acc[mi][ni][1] * alpha;
            v1.x = acc[mi][ni][2] * alpha; v1.y = acc[mi][ni][3] * alpha;
            if (EPI == 1) {
                if (mr < M) {
                    float2 r0 = *reinterpret_cast<const float2*>(R + (long long)mr * ldc + nc);
                    v0.x += r0.x; v0.y += r0.y;
                }
                if (mr + 8 < M) {
                    float2 r1 = *reinterpret_cast<const float2*>(R + (long long)(mr + 8) * ldc + nc);
                    v1.x += r1.x; v1.y += r1.y;
                }
            }
            if (EPI == 2) {
                v0.x = gelu_f(v0.x); v0.y = gelu_f(v0.y);
                v1.x = gelu_f(v1.x); v1.y = gelu_f(v1.y);
            }
            if (mr < M)
                *reinterpret_cast<float2*>(C + (long long)mr * ldc + nc) = v0;
            if (mr + 8 < M)
                *reinterpret_cast<float2*>(C + (long long)(mr + 8) * ldc + nc) = v1;
        }
    }
}

// ---------------------------------------------------------------------------
// LayerNorm over F for each (c, w). Block = (32 w-lanes, 8 f-threads).
// ---------------------------------------------------------------------------
__global__ void layernorm_kernel(const float* __restrict__ x,
                                 const float* __restrict__ g,
                                 const float* __restrict__ b,
                                 float* __restrict__ out)
{
    int w  = blockIdx.x * 32 + threadIdx.x;
    int c  = blockIdx.y;
    int fz = threadIdx.y;
    const float* xp = x + (long long)c * F_DIM * W_DIM + w;
    float s = 0.f, ss = 0.f;
    for (int f = fz; f < F_DIM; f += 8) {
        float v = xp[(long long)f * W_DIM];
        s += v; ss += v * v;
    }
    __shared__ float sh_s[8][33], sh_q[8][33];
    sh_s[fz][threadIdx.x] = s;
    sh_q[fz][threadIdx.x] = ss;
    __syncthreads();
    if (fz == 0) {
        float ts = 0.f, tq = 0.f;
        #pragma unroll
        for (int i = 0; i < 8; i++) { ts += sh_s[i][threadIdx.x]; tq += sh_q[i][threadIdx.x]; }
        float mu  = ts * (1.f / F_DIM);
        float var = tq * (1.f / F_DIM) - mu * mu;
        sh_s[0][threadIdx.x] = mu;
        sh_q[0][threadIdx.x] = rsqrtf(var + 1e-5f);
    }
    __syncthreads();
    float mu = sh_s[0][threadIdx.x];
    float rs = sh_q[0][threadIdx.x];
    float* op = out + (long long)c * F_DIM * W_DIM + w;
    for (int f = fz; f < F_DIM; f += 8) {
        float v = xp[(long long)f * W_DIM];
        op[(long long)f * W_DIM] = (v - mu) * rs * g[f] + b[f];
    }
}

// ---------------------------------------------------------------------------
// RoPE: reads p[(c*1024 + h*64 + d)*512 + w], writes same layout.
// ---------------------------------------------------------------------------
__global__ void rope_kernel(const float* __restrict__ p,
                            const float* __restrict__ freqs,
                            float* __restrict__ qr)
{
    int w  = blockIdx.x * 32 + threadIdx.x;
    int ch = blockIdx.y;                       // c*16 + h
    long long base = (long long)ch * D_DIM * W_DIM + w;
    for (int d2 = threadIdx.y; d2 < 32; d2 += 8) {
        float e = p[base + (long long)(2 * d2)     * W_DIM];
        float o = p[base + (long long)(2 * d2 + 1) * W_DIM];
        float qe, qo;
        if (d2 < 16) {
            float ang = (float)w * freqs[d2];
            float sn, cs;
            sincosf(ang, &sn, &cs);
            qe = e * cs - o * sn;
            qo = o * cs + e * sn;
        } else {
            qe = e; qo = o;
        }
        qr[base + (long long)(2 * d2)     * W_DIM] = qe;
        qr[base + (long long)(2 * d2 + 1) * W_DIM] = qo;
    }
}

// ---------------------------------------------------------------------------
// Row softmax over 512 elements, one warp per row. Block (32, 8).
// ---------------------------------------------------------------------------
__global__ void softmax_kernel(float* __restrict__ S)
{
    int row  = blockIdx.x * 8 + threadIdx.y;
    int lane = threadIdx.x;
    float* r = S + (long long)row * W_DIM;
    float v[16];
    float m = -1e30f;
    #pragma unroll
    for (int i = 0; i < 16; i++) { v[i] = r[lane + 32 * i]; m = fmaxf(m, v[i]); }
    #pragma unroll
    for (int off = 16; off; off >>= 1) m = fmaxf(m, __shfl_xor_sync(0xFFFFFFFFu, m, off));
    float s = 0.f;
    #pragma unroll
    for (int i = 0; i < 16; i++) { v[i] = __expf(v[i] - m); s += v[i]; }
    #pragma unroll
    for (int off = 16; off; off >>= 1) s += __shfl_xor_sync(0xFFFFFFFFu, s, off);
    float inv = 1.f / s;
    #pragma unroll
    for (int i = 0; i < 16; i++) r[lane + 32 * i] = v[i] * inv;
}

// ---------------------------------------------------------------------------
// Launch
// ---------------------------------------------------------------------------
extern "C" void kernel_launch(void* const* d_in, const int* in_sizes, int n_in,
                              void* d_out, int out_size)
{
    (void)in_sizes; (void)n_in; (void)out_size;
    const float* x   = (const float*)d_in[0];
    const float* g1  = (const float*)d_in[1];
    const float* b1  = (const float*)d_in[2];
    const float* wq  = (const float*)d_in[3];
    const float* wo  = (const float*)d_in[4];
    const float* fr  = (const float*)d_in[5];
    const float* g2  = (const float*)d_in[6];
    const float* b2  = (const float*)d_in[7];
    const float* w1  = (const float*)d_in[8];
    const float* w2  = (const float*)d_in[9];
    float* out = (float*)d_out;

    float *z, *p, *qr, *s, *oP, *x2, *z2, *h;
    cudaGetSymbolAddress((void**)&z,  g_z);
    cudaGetSymbolAddress((void**)&p,  g_p);
    cudaGetSymbolAddress((void**)&qr, g_qr);
    cudaGetSymbolAddress((void**)&s,  g_s);
    cudaGetSymbolAddress((void**)&oP, g_oP);
    cudaGetSymbolAddress((void**)&x2, g_x2);
    cudaGetSymbolAddress((void**)&z2, g_z2);
    cudaGetSymbolAddress((void**)&h,  g_h);

    const long long sFW  = (long long)F_DIM * W_DIM;        // 524288
    const long long sHD  = (long long)D_DIM * W_DIM;        // 32768 (per-head)
    const long long sS   = (long long)W_DIM * W_DIM;        // 262144
    const long long sWqq = (long long)F_DIM * F_DIM;        // 1048576
    const long long sW1  = (long long)FE_DIM * F_DIM;       // 4194304
    const long long sH   = (long long)FE_DIM * W_DIM;       // 2097152

    dim3 ln_grid(W_DIM / 32, C_DIM), ln_blk(32, 8);

    // 1. z = frame_norm(x)
    layernorm_kernel<<<ln_grid, ln_blk>>>(x, g1, b1, z);

    // 2. p = Wq @ z   (per channel, M=1024 N=512 K=1024, NN)
    tgemm_kernel<0, 0, 0><<<dim3(4, 8, 8), 256>>>(
        1024, 512, 1024, wq, 1024, sWqq, z, 512, sFW, p, 512, sFW, nullptr, 0, 1.f);

    // 3. qr = rope(p)
    rope_kernel<<<dim3(W_DIM / 32, C_DIM * H_DIM), dim3(32, 8)>>>(p, fr, qr);

    // 4. S = (qr^T qr) / 32   (TN, per head: M=N=512 K=64, 128 batches)
    tgemm_kernel<1, 0, 0><<<dim3(4, 4, 128), 256>>>(
        512, 512, 64, qr, 512, sHD, qr, 512, sHD, s, 512, sS, nullptr, 0, 0.03125f);

    // 5. softmax rows
    softmax_kernel<<<(C_DIM * H_DIM * W_DIM) / 8, dim3(32, 8)>>>(s);

    // 6. oP[d, q] = sum_k V[d,k] * S[q,k]   (NT, M=64 N=512 K=512; V = p)
    tgemm_kernel<0, 1, 0><<<dim3(4, 1, 128), 256>>>(
        64, 512, 512, p, 512, sHD, s, 512, sS, oP, 512, sHD, nullptr, 0, 1.f);

    // 7. x2 = x + Wo @ oP
    tgemm_kernel<0, 0, 1><<<dim3(4, 8, 8), 256>>>(
        1024, 512, 1024, wo, 1024, sWqq, oP, 512, sFW, x2, 512, sFW, x, sFW, 1.f);

    // 8. z2 = frame_norm(x2)
    layernorm_kernel<<<ln_grid, ln_blk>>>(x2, g2, b2, z2);

    // 9. h = gelu(W1 @ z2)   (M=4096 N=512 K=1024)
    tgemm_kernel<0, 0, 2><<<dim3(4, 32, 8), 256>>>(
        4096, 512, 1024, w1, 1024, sW1, z2, 512, sFW, h, 512, sH, nullptr, 0, 1.f);

    // 10. out = x2 + W2 @ h   (M=1024 N=512 K=4096)
    tgemm_kernel<0, 0, 1><<<dim3(4, 8, 8), 256>>>(
        1024, 512, 4096, w2, 4096, sW1, h, 512, sH, out, 512, sFW, x2, sFW, 1.f);
}